// round 5
// baseline (speedup 1.0000x reference)
#include <cuda_runtime.h>
#include <cuda_fp16.h>
#include <math.h>
#include <stdint.h>

#define NN 50000
#define EE 1600000
#define D 128
#define DAGG 384
#define DCAT 1152
#define CAP 128
#define AVG_D_LOG_F 3.4965075614664802f

// ---------------- static scratch --------------------------------------------
__device__ int g_cnt[NN];
__device__ int g_srcl[(size_t)NN * CAP];
__device__ float g_e1[NN];
__device__ __align__(16) __half g_hh[(size_t)NN * D];       // h in fp16
__device__ __align__(16) __half g_aggh[(size_t)NN * DAGG];  // agg fp16 [N,384]
__device__ __align__(16) __half g_Wh[(size_t)DCAT * D];     // W in fp16 [1152,128]

// ---------------- helpers ---------------------------------------------------
__device__ __forceinline__ float4 h4conv(uint2 u) {
    __half2 a = *reinterpret_cast<__half2*>(&u.x);
    __half2 b = *reinterpret_cast<__half2*>(&u.y);
    float2 fa = __half22float2(a);
    float2 fb = __half22float2(b);
    return make_float4(fa.x, fa.y, fb.x, fb.y);
}

__device__ __forceinline__ uint2 pack4(float4 v) {
    uint2 r;
    __half2 lo = __floats2half2_rn(v.x, v.y);
    __half2 hi = __floats2half2_rn(v.z, v.w);
    r.x = *reinterpret_cast<uint32_t*>(&lo);
    r.y = *reinterpret_cast<uint32_t*>(&hi);
    return r;
}

__device__ __forceinline__ void mma_f16(float* c, const uint32_t* a,
                                        uint32_t b0, uint32_t b1) {
    asm volatile(
        "mma.sync.aligned.m16n8k16.row.col.f32.f16.f16.f32 "
        "{%0,%1,%2,%3}, {%4,%5,%6,%7}, {%8,%9}, {%0,%1,%2,%3};\n"
        : "+f"(c[0]), "+f"(c[1]), "+f"(c[2]), "+f"(c[3])
        : "r"(a[0]), "r"(a[1]), "r"(a[2]), "r"(a[3]), "r"(b0), "r"(b1));
}

__device__ __forceinline__ void ldm_x4(uint32_t* r, uint32_t addr) {
    asm volatile("ldmatrix.sync.aligned.m8n8.x4.shared.b16 {%0,%1,%2,%3}, [%4];"
                 : "=r"(r[0]), "=r"(r[1]), "=r"(r[2]), "=r"(r[3]) : "r"(addr));
}

__device__ __forceinline__ void ldm_x4t(uint32_t* r, uint32_t addr) {
    asm volatile("ldmatrix.sync.aligned.m8n8.x4.trans.shared.b16 {%0,%1,%2,%3}, [%4];"
                 : "=r"(r[0]), "=r"(r[1]), "=r"(r[2]), "=r"(r[3]) : "r"(addr));
}

__device__ __forceinline__ void cp16(uint32_t smem_addr, const void* gptr) {
    asm volatile("cp.async.cg.shared.global [%0], [%1], 16;\n"
                 :: "r"(smem_addr), "l"(gptr));
}

__device__ __forceinline__ uint32_t hscale(uint32_t a, uint32_t coef2) {
    __half2 r = __hmul2(*reinterpret_cast<__half2*>(&a),
                        *reinterpret_cast<__half2*>(&coef2));
    return *reinterpret_cast<uint32_t*>(&r);
}

// ---------------- kernel 1: prep --------------------------------------------
__global__ void k_prep(const float2* __restrict__ h2in, const float* __restrict__ eig,
                       const float2* __restrict__ W2) {
    int idx = blockIdx.x * blockDim.x + threadIdx.x;
    if (idx < NN * 64) {
        float2 v = h2in[idx];
        reinterpret_cast<__half2*>(g_hh)[idx] = __floats2half2_rn(v.x, v.y);
    }
    if (idx < DCAT * 64) {
        float2 v = W2[idx];
        reinterpret_cast<__half2*>(g_Wh)[idx] = __floats2half2_rn(v.x, v.y);
    }
    if (idx < NN) {
        g_cnt[idx] = 0;
        g_e1[idx] = eig[(size_t)idx * 4];
    }
}

// ---------------- kernel 2: bucket fill --------------------------------------
__global__ void k_fill(const int4* __restrict__ src4, const int4* __restrict__ dst4) {
    int i = blockIdx.x * blockDim.x + threadIdx.x;
    if (i >= EE / 4) return;
    int4 d = dst4[i];
    int4 s = src4[i];
    int p0 = atomicAdd(&g_cnt[d.x], 1);
    int p1 = atomicAdd(&g_cnt[d.y], 1);
    int p2 = atomicAdd(&g_cnt[d.z], 1);
    int p3 = atomicAdd(&g_cnt[d.w], 1);
    g_srcl[(size_t)d.x * CAP + p0] = s.x;
    g_srcl[(size_t)d.y * CAP + p1] = s.y;
    g_srcl[(size_t)d.z * CAP + p2] = s.z;
    g_srcl[(size_t)d.w * CAP + p3] = s.w;
}

// ---------------- kernel 3: warp-per-node reduce -> agg fp16 [N,384] ---------
__global__ __launch_bounds__(256) void k_reduce() {
    int wid = threadIdx.x >> 5;
    int lane = threadIdx.x & 31;
    int node = blockIdx.x * 8 + wid;
    if (node >= NN) return;
    int deg = g_cnt[node];
    size_t base = (size_t)node * CAP;
    float e1d = g_e1[node];
    const uint2* h2 = reinterpret_cast<const uint2*>(g_hh);

    float sx = 0.f, sy = 0.f, sz = 0.f, sw = 0.f;
    float mxx = -3.402823466e38f, mxy = mxx, mxz = mxx, mxw = mxx;
    float dx = 0.f, dy = 0.f, dz = 0.f, dw = 0.f;
    float wsum = 0.f;

    int j = 0;
    for (; j + 2 <= deg; j += 2) {
        int s0 = g_srcl[base + j];
        int s1 = g_srcl[base + j + 1];
        float w0 = fabsf(g_e1[s0] - e1d);
        float w1 = fabsf(g_e1[s1] - e1d);
        float4 v0 = h4conv(h2[(size_t)s0 * 32 + lane]);
        float4 v1 = h4conv(h2[(size_t)s1 * 32 + lane]);
        sx += v0.x; sy += v0.y; sz += v0.z; sw += v0.w;
        mxx = fmaxf(mxx, v0.x); mxy = fmaxf(mxy, v0.y);
        mxz = fmaxf(mxz, v0.z); mxw = fmaxf(mxw, v0.w);
        dx = fmaf(w0, v0.x, dx); dy = fmaf(w0, v0.y, dy);
        dz = fmaf(w0, v0.z, dz); dw = fmaf(w0, v0.w, dw);
        wsum += w0;
        sx += v1.x; sy += v1.y; sz += v1.z; sw += v1.w;
        mxx = fmaxf(mxx, v1.x); mxy = fmaxf(mxy, v1.y);
        mxz = fmaxf(mxz, v1.z); mxw = fmaxf(mxw, v1.w);
        dx = fmaf(w1, v1.x, dx); dy = fmaf(w1, v1.y, dy);
        dz = fmaf(w1, v1.z, dz); dw = fmaf(w1, v1.w, dw);
        wsum += w1;
    }
    if (j < deg) {
        int s0 = g_srcl[base + j];
        float w0 = fabsf(g_e1[s0] - e1d);
        float4 v0 = h4conv(h2[(size_t)s0 * 32 + lane]);
        sx += v0.x; sy += v0.y; sz += v0.z; sw += v0.w;
        mxx = fmaxf(mxx, v0.x); mxy = fmaxf(mxy, v0.y);
        mxz = fmaxf(mxz, v0.z); mxw = fmaxf(mxw, v0.w);
        dx = fmaf(w0, v0.x, dx); dy = fmaf(w0, v0.y, dy);
        dz = fmaf(w0, v0.z, dz); dw = fmaf(w0, v0.w, dw);
        wsum += w0;
    }

    float invd = 1.f / (float)(deg > 0 ? deg : 1);
    float invw = 1.f / (wsum + 1e-30f);
    if (deg == 0) { mxx = 0.f; mxy = 0.f; mxz = 0.f; mxw = 0.f; }

    uint2* o = reinterpret_cast<uint2*>(g_aggh) + (size_t)node * 96;
    o[lane]      = pack4(make_float4(sx * invd, sy * invd, sz * invd, sw * invd));
    o[32 + lane] = pack4(make_float4(mxx, mxy, mxz, mxw));
    o[64 + lane] = pack4(make_float4(dx * invw, dy * invw, dz * invw, dw * invw));
}

// ---------------- kernel 4: fused triple-pass GEMM + epilogue ----------------
// out[r,c] = epi( sum_g coef_g(r) * (agg[r,:] @ W[g*384:(g+1)*384, c]) )
// 36 steps over (kt 0..11, g 0..2); A frag cached in regs across g.
#define BM 128
#define BN 128
#define BK 32
#define NSTEP 36

__global__ __launch_bounds__(256) void k_gemm(
    const float* __restrict__ h, const float* __restrict__ snorm,
    const float* __restrict__ bias, const float* __restrict__ gamma,
    const float* __restrict__ beta, const float* __restrict__ mean,
    const float* __restrict__ var, float* __restrict__ out) {
    __shared__ __half As[2][BM][40];    // 20480 B
    __shared__ __half Bs[2][BK][136];   // 17408 B
    __shared__ float samp[BM], satt[BM], ssn[BM];

    int tid = threadIdx.x;
    int wid = tid >> 5;
    int lane = tid & 31;
    int t = lane & 3;
    int gid = lane >> 2;
    int wr = wid & 3;   // rows wr*32
    int wc = wid >> 2;  // cols wc*64
    int rowBlock = blockIdx.x * BM;

    // per-row scaler coefficients
    for (int i = tid; i < BM; i += 256) {
        int r = rowBlock + i;
        float amp = 0.f, att = 0.f, sn = 0.f;
        if (r < NN) {
            int deg = g_cnt[r];
            float logD = logf((float)deg + 1.0f);
            amp = logD * (1.0f / AVG_D_LOG_F);
            att = fminf(AVG_D_LOG_F / fmaxf(logD, 1e-6f), 60000.f);
            sn = snorm[r];
        }
        samp[i] = amp;
        satt[i] = att;
        ssn[i] = sn;
    }

    // A cp.async lanes: 2 chunks/thread (rows tid>>2, +64; chunk tid&3)
    int a_row = tid >> 2, a_chk = tid & 3;
    int ar0 = rowBlock + a_row; if (ar0 > NN - 1) ar0 = NN - 1;
    int ar1 = ar0 + 64; if (ar1 > NN - 1) ar1 = NN - 1;
    if (rowBlock + a_row + 64 > NN - 1) ar1 = NN - 1;
    const __half* a_src0 = g_aggh + (size_t)ar0 * DAGG + a_chk * 8;
    const __half* a_src1 = g_aggh + (size_t)ar1 * DAGG + a_chk * 8;
    uint32_t a_dst0 = (uint32_t)__cvta_generic_to_shared(&As[0][a_row][a_chk * 8]);
    uint32_t a_dst1 = a_dst0 + 64 * 80;

    // B cp.async lanes: 2 chunks/thread (rows tid>>4, +16; col tid&15)
    int b_row = tid >> 4, b_col = tid & 15;
    const __half* b_src0 = g_Wh + (size_t)b_row * D + b_col * 8;         // + step row offset
    const __half* b_src1 = g_Wh + (size_t)(b_row + 16) * D + b_col * 8;
    uint32_t b_dst0 = (uint32_t)__cvta_generic_to_shared(&Bs[0][b_row][b_col * 8]);
    uint32_t b_dst1 = b_dst0 + 16 * 272;

    float c[2][8][4];
#pragma unroll
    for (int mt = 0; mt < 2; mt++)
#pragma unroll
        for (int nt = 0; nt < 8; nt++)
#pragma unroll
            for (int k = 0; k < 4; k++) c[mt][nt][k] = 0.f;

    // prologue: A(kt=0) -> Abuf0, B(step0: g=0,kt=0) -> Bbuf0
    cp16(a_dst0, a_src0);
    cp16(a_dst1, a_src1);
    cp16(b_dst0, b_src0);
    cp16(b_dst1, b_src1);
    asm volatile("cp.async.commit_group;\n");

    __syncthreads();  // coef arrays visible

    uint32_t amp2[2][2], att2[2][2];
#pragma unroll
    for (int mt = 0; mt < 2; mt++) {
        int r0 = wr * 32 + mt * 16 + gid;
        __half2 a0 = __float2half2_rn(samp[r0]);
        __half2 a1 = __float2half2_rn(samp[r0 + 8]);
        __half2 t0 = __float2half2_rn(satt[r0]);
        __half2 t1 = __float2half2_rn(satt[r0 + 8]);
        amp2[mt][0] = *reinterpret_cast<uint32_t*>(&a0);
        amp2[mt][1] = *reinterpret_cast<uint32_t*>(&a1);
        att2[mt][0] = *reinterpret_cast<uint32_t*>(&t0);
        att2[mt][1] = *reinterpret_cast<uint32_t*>(&t1);
    }

    uint32_t a_lm = (uint32_t)__cvta_generic_to_shared(
        &As[0][wr * 32 + (lane & 15)][(lane >> 4) << 3]);
    uint32_t b_lm = (uint32_t)__cvta_generic_to_shared(
        &Bs[0][lane & 15][wc * 64 + ((lane >> 4) << 3)]);

    uint32_t afrag[2][2][4];  // [ks][mt][4] cached across g

    for (int s = 0; s < NSTEP; s++) {
        int kt = s / 3;
        int g = s - kt * 3;
        int bbuf = s & 1;
        int abuf = kt & 1;
        if (s + 1 < NSTEP) {
            int sn1 = s + 1;
            int kt1 = sn1 / 3;
            int g1 = sn1 - kt1 * 3;
            // B rows for step sn1: g1*384 + kt1*32
            size_t brow = (size_t)(g1 * DAGG + kt1 * BK) * D;
            uint32_t bo = (sn1 & 1) * 8704;
            cp16(b_dst0 + bo, b_src0 + brow);
            cp16(b_dst1 + bo, b_src1 + brow);
            if (g1 == 0) {  // new kt begins at next step
                uint32_t ao = (kt1 & 1) * 10240;
                size_t koff = (size_t)kt1 * BK;
                cp16(a_dst0 + ao, a_src0 + koff);
                cp16(a_dst1 + ao, a_src1 + koff);
            }
            asm volatile("cp.async.commit_group;\n");
            asm volatile("cp.async.wait_group 1;\n");
        } else {
            asm volatile("cp.async.wait_group 0;\n");
        }
        __syncthreads();

        uint32_t a_base = a_lm + abuf * 10240;
        uint32_t b_base = b_lm + bbuf * 8704;
#pragma unroll
        for (int ks = 0; ks < 2; ks++) {
            if (g == 0) {
                ldm_x4(afrag[ks][0], a_base + ks * 32);
                ldm_x4(afrag[ks][1], a_base + 16 * 80 + ks * 32);
            }
            uint32_t au[2][4];
#pragma unroll
            for (int mt = 0; mt < 2; mt++) {
                if (g == 0) {
                    au[mt][0] = afrag[ks][mt][0]; au[mt][1] = afrag[ks][mt][1];
                    au[mt][2] = afrag[ks][mt][2]; au[mt][3] = afrag[ks][mt][3];
                } else if (g == 1) {
                    au[mt][0] = hscale(afrag[ks][mt][0], amp2[mt][0]);
                    au[mt][1] = hscale(afrag[ks][mt][1], amp2[mt][1]);
                    au[mt][2] = hscale(afrag[ks][mt][2], amp2[mt][0]);
                    au[mt][3] = hscale(afrag[ks][mt][3], amp2[mt][1]);
                } else {
                    au[mt][0] = hscale(afrag[ks][mt][0], att2[mt][0]);
                    au[mt][1] = hscale(afrag[ks][mt][1], att2[mt][1]);
                    au[mt][2] = hscale(afrag[ks][mt][2], att2[mt][0]);
                    au[mt][3] = hscale(afrag[ks][mt][3], att2[mt][1]);
                }
            }
#pragma unroll
            for (int p = 0; p < 4; p++) {
                uint32_t bfr[4];
                ldm_x4t(bfr, b_base + ks * 16 * 272 + p * 32);
#pragma unroll
                for (int mt = 0; mt < 2; mt++) {
                    mma_f16(c[mt][p * 2], au[mt], bfr[0], bfr[1]);
                    mma_f16(c[mt][p * 2 + 1], au[mt], bfr[2], bfr[3]);
                }
            }
        }
        __syncthreads();
    }

    // fused epilogue
#pragma unroll
    for (int nt = 0; nt < 8; nt++) {
        int col = wc * 64 + nt * 8 + 2 * t;
        float2 bi = *(const float2*)(bias + col);
        float2 mn = *(const float2*)(mean + col);
        float2 vr = *(const float2*)(var + col);
        float2 gm = *(const float2*)(gamma + col);
        float2 bt = *(const float2*)(beta + col);
        float sc0 = rsqrtf(vr.x + 1e-5f) * gm.x;
        float sc1 = rsqrtf(vr.y + 1e-5f) * gm.y;
        float sh0 = bt.x - mn.x * sc0;
        float sh1 = bt.y - mn.y * sc1;
#pragma unroll
        for (int mt = 0; mt < 2; mt++) {
#pragma unroll
            for (int p = 0; p < 2; p++) {
                int rloc = wr * 32 + mt * 16 + gid + p * 8;
                int r = rowBlock + rloc;
                if (r < NN) {
                    float sn = ssn[rloc];
                    float v0 = (c[mt][nt][p * 2 + 0] + bi.x) * sn;
                    float v1 = (c[mt][nt][p * 2 + 1] + bi.y) * sn;
                    v0 = fmaxf(fmaf(v0, sc0, sh0), 0.f);
                    v1 = fmaxf(fmaf(v1, sc1, sh1), 0.f);
                    float2 hres = *(const float2*)(h + (size_t)r * D + col);
                    *(float2*)(out + (size_t)r * D + col) =
                        make_float2(hres.x + v0, hres.y + v1);
                }
            }
        }
    }
}

// ---------------- launch ----------------------------------------------------
extern "C" void kernel_launch(void* const* d_in, const int* in_sizes, int n_in,
                              void* d_out, int out_size) {
    const float* h = (const float*)d_in[0];
    const float* eig = (const float*)d_in[1];
    const float* snorm = (const float*)d_in[2];
    const float* W = (const float*)d_in[3];
    const float* bias = (const float*)d_in[4];
    const float* gamma = (const float*)d_in[5];
    const float* beta = (const float*)d_in[6];
    const float* mean = (const float*)d_in[7];
    const float* var = (const float*)d_in[8];
    const int* esrc = (const int*)d_in[9];
    const int* edst = (const int*)d_in[10];
    float* out = (float*)d_out;

    k_prep<<<(NN * 64 + 255) / 256, 256>>>((const float2*)h, eig, (const float2*)W);
    k_fill<<<(EE / 4 + 255) / 256, 256>>>((const int4*)esrc, (const int4*)edst);
    k_reduce<<<(NN + 7) / 8, 256>>>();
    k_gemm<<<(NN + BM - 1) / BM, 256>>>(h, snorm, bias, gamma, beta, mean, var, out);
}

// round 6
// speedup vs baseline: 1.2023x; 1.2023x over previous
#include <cuda_runtime.h>
#include <cuda_fp16.h>
#include <math.h>
#include <stdint.h>

#define NN 50000
#define EE 1600000
#define D 128
#define DAGG 384
#define DCAT 1152
#define CAP 128
#define AVG_D_LOG_F 3.4965075614664802f

// ---------------- static scratch --------------------------------------------
__device__ int g_cnt[NN];
__device__ int g_srcl[(size_t)NN * CAP];
__device__ float g_e1[NN];
__device__ __align__(16) __half g_hh[(size_t)NN * D];       // h in fp16
__device__ __align__(16) __half g_aggh[(size_t)NN * DAGG];  // agg fp16 [N,384]
__device__ __align__(16) __half g_Wh[(size_t)DCAT * D];     // W in fp16 [1152,128]

// ---------------- helpers ---------------------------------------------------
__device__ __forceinline__ float4 h4conv(uint2 u) {
    __half2 a = *reinterpret_cast<__half2*>(&u.x);
    __half2 b = *reinterpret_cast<__half2*>(&u.y);
    float2 fa = __half22float2(a);
    float2 fb = __half22float2(b);
    return make_float4(fa.x, fa.y, fb.x, fb.y);
}

__device__ __forceinline__ uint2 pack4(float4 v) {
    uint2 r;
    __half2 lo = __floats2half2_rn(v.x, v.y);
    __half2 hi = __floats2half2_rn(v.z, v.w);
    r.x = *reinterpret_cast<uint32_t*>(&lo);
    r.y = *reinterpret_cast<uint32_t*>(&hi);
    return r;
}

__device__ __forceinline__ void mma_f16(float* c, const uint32_t* a,
                                        uint32_t b0, uint32_t b1) {
    asm volatile(
        "mma.sync.aligned.m16n8k16.row.col.f32.f16.f16.f32 "
        "{%0,%1,%2,%3}, {%4,%5,%6,%7}, {%8,%9}, {%0,%1,%2,%3};\n"
        : "+f"(c[0]), "+f"(c[1]), "+f"(c[2]), "+f"(c[3])
        : "r"(a[0]), "r"(a[1]), "r"(a[2]), "r"(a[3]), "r"(b0), "r"(b1));
}

__device__ __forceinline__ void ldm_x4(uint32_t* r, uint32_t addr) {
    asm volatile("ldmatrix.sync.aligned.m8n8.x4.shared.b16 {%0,%1,%2,%3}, [%4];"
                 : "=r"(r[0]), "=r"(r[1]), "=r"(r[2]), "=r"(r[3]) : "r"(addr));
}

__device__ __forceinline__ void ldm_x4t(uint32_t* r, uint32_t addr) {
    asm volatile("ldmatrix.sync.aligned.m8n8.x4.trans.shared.b16 {%0,%1,%2,%3}, [%4];"
                 : "=r"(r[0]), "=r"(r[1]), "=r"(r[2]), "=r"(r[3]) : "r"(addr));
}

__device__ __forceinline__ void cp16(uint32_t smem_addr, const void* gptr) {
    asm volatile("cp.async.cg.shared.global [%0], [%1], 16;\n"
                 :: "r"(smem_addr), "l"(gptr));
}

__device__ __forceinline__ uint32_t hscale(uint32_t a, uint32_t coef2) {
    __half2 r = __hmul2(*reinterpret_cast<__half2*>(&a),
                        *reinterpret_cast<__half2*>(&coef2));
    return *reinterpret_cast<uint32_t*>(&r);
}

// ---------------- kernel 1: prep --------------------------------------------
__global__ void k_prep(const float2* __restrict__ h2in, const float* __restrict__ eig,
                       const float2* __restrict__ W2) {
    int idx = blockIdx.x * blockDim.x + threadIdx.x;
    if (idx < NN * 64) {
        float2 v = h2in[idx];
        reinterpret_cast<__half2*>(g_hh)[idx] = __floats2half2_rn(v.x, v.y);
    }
    if (idx < DCAT * 64) {
        float2 v = W2[idx];
        reinterpret_cast<__half2*>(g_Wh)[idx] = __floats2half2_rn(v.x, v.y);
    }
    if (idx < NN) {
        g_cnt[idx] = 0;
        g_e1[idx] = eig[(size_t)idx * 4];
    }
}

// ---------------- kernel 2: bucket fill --------------------------------------
__global__ void k_fill(const int4* __restrict__ src4, const int4* __restrict__ dst4) {
    int i = blockIdx.x * blockDim.x + threadIdx.x;
    if (i >= EE / 4) return;
    int4 d = dst4[i];
    int4 s = src4[i];
    int p0 = atomicAdd(&g_cnt[d.x], 1);
    int p1 = atomicAdd(&g_cnt[d.y], 1);
    int p2 = atomicAdd(&g_cnt[d.z], 1);
    int p3 = atomicAdd(&g_cnt[d.w], 1);
    g_srcl[(size_t)d.x * CAP + p0] = s.x;
    g_srcl[(size_t)d.y * CAP + p1] = s.y;
    g_srcl[(size_t)d.z * CAP + p2] = s.z;
    g_srcl[(size_t)d.w * CAP + p3] = s.w;
}

// ---------------- kernel 3: warp-per-node reduce (4-edge ILP) ----------------
__global__ __launch_bounds__(256) void k_reduce() {
    int wid = threadIdx.x >> 5;
    int lane = threadIdx.x & 31;
    int node = blockIdx.x * 8 + wid;
    if (node >= NN) return;
    int deg = g_cnt[node];
    size_t base = (size_t)node * CAP;
    float e1d = g_e1[node];
    const uint2* h2 = reinterpret_cast<const uint2*>(g_hh);

    float sx = 0.f, sy = 0.f, sz = 0.f, sw = 0.f;
    float mxx = -3.402823466e38f, mxy = mxx, mxz = mxx, mxw = mxx;
    float dx = 0.f, dy = 0.f, dz = 0.f, dw = 0.f;
    float wsum = 0.f;

    int j = 0;
    for (; j + 4 <= deg; j += 4) {
        int s0 = g_srcl[base + j];
        int s1 = g_srcl[base + j + 1];
        int s2 = g_srcl[base + j + 2];
        int s3 = g_srcl[base + j + 3];
        float w0 = fabsf(g_e1[s0] - e1d);
        float w1 = fabsf(g_e1[s1] - e1d);
        float w2 = fabsf(g_e1[s2] - e1d);
        float w3 = fabsf(g_e1[s3] - e1d);
        uint2 u0 = h2[(size_t)s0 * 32 + lane];
        uint2 u1 = h2[(size_t)s1 * 32 + lane];
        uint2 u2 = h2[(size_t)s2 * 32 + lane];
        uint2 u3 = h2[(size_t)s3 * 32 + lane];
        float4 v0 = h4conv(u0);
        float4 v1 = h4conv(u1);
        float4 v2 = h4conv(u2);
        float4 v3 = h4conv(u3);
        sx += v0.x + v1.x + v2.x + v3.x;
        sy += v0.y + v1.y + v2.y + v3.y;
        sz += v0.z + v1.z + v2.z + v3.z;
        sw += v0.w + v1.w + v2.w + v3.w;
        mxx = fmaxf(fmaxf(mxx, fmaxf(v0.x, v1.x)), fmaxf(v2.x, v3.x));
        mxy = fmaxf(fmaxf(mxy, fmaxf(v0.y, v1.y)), fmaxf(v2.y, v3.y));
        mxz = fmaxf(fmaxf(mxz, fmaxf(v0.z, v1.z)), fmaxf(v2.z, v3.z));
        mxw = fmaxf(fmaxf(mxw, fmaxf(v0.w, v1.w)), fmaxf(v2.w, v3.w));
        dx = fmaf(w0, v0.x, fmaf(w1, v1.x, fmaf(w2, v2.x, fmaf(w3, v3.x, dx))));
        dy = fmaf(w0, v0.y, fmaf(w1, v1.y, fmaf(w2, v2.y, fmaf(w3, v3.y, dy))));
        dz = fmaf(w0, v0.z, fmaf(w1, v1.z, fmaf(w2, v2.z, fmaf(w3, v3.z, dz))));
        dw = fmaf(w0, v0.w, fmaf(w1, v1.w, fmaf(w2, v2.w, fmaf(w3, v3.w, dw))));
        wsum += w0 + w1 + w2 + w3;
    }
    for (; j < deg; j++) {
        int s0 = g_srcl[base + j];
        float w0 = fabsf(g_e1[s0] - e1d);
        float4 v0 = h4conv(h2[(size_t)s0 * 32 + lane]);
        sx += v0.x; sy += v0.y; sz += v0.z; sw += v0.w;
        mxx = fmaxf(mxx, v0.x); mxy = fmaxf(mxy, v0.y);
        mxz = fmaxf(mxz, v0.z); mxw = fmaxf(mxw, v0.w);
        dx = fmaf(w0, v0.x, dx); dy = fmaf(w0, v0.y, dy);
        dz = fmaf(w0, v0.z, dz); dw = fmaf(w0, v0.w, dw);
        wsum += w0;
    }

    float invd = 1.f / (float)(deg > 0 ? deg : 1);
    float invw = 1.f / (wsum + 1e-30f);
    if (deg == 0) { mxx = 0.f; mxy = 0.f; mxz = 0.f; mxw = 0.f; }

    uint2* o = reinterpret_cast<uint2*>(g_aggh) + (size_t)node * 96;
    o[lane]      = pack4(make_float4(sx * invd, sy * invd, sz * invd, sw * invd));
    o[32 + lane] = pack4(make_float4(mxx, mxy, mxz, mxw));
    o[64 + lane] = pack4(make_float4(dx * invw, dy * invw, dz * invw, dw * invw));
}

// ---------------- kernel 4: fused triple-B GEMM + epilogue -------------------
// out[r,c] = epi( sum_g coef_g(r) * (agg[r,:] @ W[g*384:(g+1)*384, c]) )
// All 3 B groups staged per k-tile: 48 MMAs between syncs, 12 steps.
#define BM 128
#define BN 128
#define BK 32
#define NKT (DAGG / BK)  // 12
// smem (halfs): As 2*128*40 = 10240 ; Bs 2*3*32*136 = 26112 ; + 384 floats
#define SM_BS 10240
#define SM_COEF 36352
#define SMEM_BYTES (36352 * 2 + 3 * 128 * 4)

__global__ __launch_bounds__(256, 2) void k_gemm(
    const float* __restrict__ h, const float* __restrict__ snorm,
    const float* __restrict__ bias, const float* __restrict__ gamma,
    const float* __restrict__ beta, const float* __restrict__ mean,
    const float* __restrict__ var, float* __restrict__ out) {
    extern __shared__ __half sh[];
    __half* As = sh;                         // [2][128][40]
    __half* Bs = sh + SM_BS;                 // [2][3][32][136]
    float* samp = (float*)(sh + SM_COEF);    // [128]
    float* satt = samp + BM;
    float* ssn = satt + BM;

    int tid = threadIdx.x;
    int wid = tid >> 5;
    int lane = tid & 31;
    int t = lane & 3;
    int gid = lane >> 2;
    int wr = wid & 3;   // rows wr*32
    int wc = wid >> 2;  // cols wc*64
    int rowBlock = blockIdx.x * BM;

    // per-row scaler coefficients
    for (int i = tid; i < BM; i += 256) {
        int r = rowBlock + i;
        float amp = 0.f, att = 0.f, sn = 0.f;
        if (r < NN) {
            int deg = g_cnt[r];
            float logD = logf((float)deg + 1.0f);
            amp = logD * (1.0f / AVG_D_LOG_F);
            att = fminf(AVG_D_LOG_F / fmaxf(logD, 1e-6f), 60000.f);
            sn = snorm[r];
        }
        samp[i] = amp;
        satt[i] = att;
        ssn[i] = sn;
    }

    // A async-copy lanes: 2 chunks/thread (rows tid>>2 and +64, chunk tid&3)
    int a_row = tid >> 2, a_chk = tid & 3;
    int ar0 = rowBlock + a_row; if (ar0 > NN - 1) ar0 = NN - 1;
    int ar1 = rowBlock + a_row + 64; if (ar1 > NN - 1) ar1 = NN - 1;
    const __half* a_src0 = g_aggh + (size_t)ar0 * DAGG + a_chk * 8;
    const __half* a_src1 = g_aggh + (size_t)ar1 * DAGG + a_chk * 8;
    uint32_t a_dst0 = (uint32_t)__cvta_generic_to_shared(As + a_row * 40 + a_chk * 8);
    uint32_t a_dst1 = a_dst0 + 64 * 80;

    // B async-copy lanes: 6 chunks/thread over [3][32][16]
    const __half* b_src[6];
    uint32_t b_dst[6];
#pragma unroll
    for (int i = 0; i < 6; i++) {
        int idx = tid + 256 * i;
        int g = idx >> 9;
        int rem = idx & 511;
        int row = rem >> 4;
        int col = rem & 15;
        b_src[i] = g_Wh + ((size_t)g * DAGG + row) * D + col * 8;
        b_dst[i] = (uint32_t)__cvta_generic_to_shared(
            Bs + g * 4352 + row * 136 + col * 8);
    }

    float c[2][8][4];
#pragma unroll
    for (int mt = 0; mt < 2; mt++)
#pragma unroll
        for (int nt = 0; nt < 8; nt++)
#pragma unroll
            for (int k = 0; k < 4; k++) c[mt][nt][k] = 0.f;

    // prefetch tile 0 (buf 0)
    cp16(a_dst0, a_src0);
    cp16(a_dst1, a_src1);
#pragma unroll
    for (int i = 0; i < 6; i++) cp16(b_dst[i], b_src[i]);
    asm volatile("cp.async.commit_group;\n");

    __syncthreads();  // coef arrays visible

    // per-thread coef half2 broadcasts (rows wr*32 + mt*16 + gid / +8)
    uint32_t amp2[2][2], att2[2][2];
#pragma unroll
    for (int mt = 0; mt < 2; mt++) {
        int r0 = wr * 32 + mt * 16 + gid;
        __half2 a0 = __float2half2_rn(samp[r0]);
        __half2 a1 = __float2half2_rn(samp[r0 + 8]);
        __half2 t0 = __float2half2_rn(satt[r0]);
        __half2 t1 = __float2half2_rn(satt[r0 + 8]);
        amp2[mt][0] = *reinterpret_cast<uint32_t*>(&a0);
        amp2[mt][1] = *reinterpret_cast<uint32_t*>(&a1);
        att2[mt][0] = *reinterpret_cast<uint32_t*>(&t0);
        att2[mt][1] = *reinterpret_cast<uint32_t*>(&t1);
    }

    // ldmatrix base addresses (buf 0)
    uint32_t a_lm = (uint32_t)__cvta_generic_to_shared(
        As + (wr * 32 + (lane & 15)) * 40 + ((lane >> 4) << 3));
    uint32_t b_lm = (uint32_t)__cvta_generic_to_shared(
        Bs + (lane & 15) * 136 + wc * 64 + ((lane >> 4) << 3));

    for (int kt = 0; kt < NKT; kt++) {
        int buf = kt & 1;
        if (kt + 1 < NKT) {
            size_t koff = (size_t)(kt + 1) * BK;
            uint32_t abufo = (buf ^ 1) * 10240;  // bytes: 128*40*2
            cp16(a_dst0 + abufo, a_src0 + koff);
            cp16(a_dst1 + abufo, a_src1 + koff);
            uint32_t bbufo = (buf ^ 1) * 26112;  // bytes: 3*32*136*2
#pragma unroll
            for (int i = 0; i < 6; i++)
                cp16(b_dst[i] + bbufo, b_src[i] + koff * D);
            asm volatile("cp.async.commit_group;\n");
            asm volatile("cp.async.wait_group 1;\n");
        } else {
            asm volatile("cp.async.wait_group 0;\n");
        }
        __syncthreads();

        uint32_t a_base = a_lm + buf * 10240;
        uint32_t b_base = b_lm + buf * 26112;
#pragma unroll
        for (int ks = 0; ks < 2; ks++) {
            uint32_t a[2][4];
            ldm_x4(a[0], a_base + ks * 32);
            ldm_x4(a[1], a_base + 16 * 80 + ks * 32);
#pragma unroll
            for (int g = 0; g < 3; g++) {
                uint32_t bfr[4][4];
#pragma unroll
                for (int p = 0; p < 4; p++)
                    ldm_x4t(bfr[p], b_base + g * 8704 + ks * 16 * 272 + p * 32);
                uint32_t au[2][4];
#pragma unroll
                for (int mt = 0; mt < 2; mt++) {
                    if (g == 0) {
                        au[mt][0] = a[mt][0]; au[mt][1] = a[mt][1];
                        au[mt][2] = a[mt][2]; au[mt][3] = a[mt][3];
                    } else if (g == 1) {
                        au[mt][0] = hscale(a[mt][0], amp2[mt][0]);
                        au[mt][1] = hscale(a[mt][1], amp2[mt][1]);
                        au[mt][2] = hscale(a[mt][2], amp2[mt][0]);
                        au[mt][3] = hscale(a[mt][3], amp2[mt][1]);
                    } else {
                        au[mt][0] = hscale(a[mt][0], att2[mt][0]);
                        au[mt][1] = hscale(a[mt][1], att2[mt][1]);
                        au[mt][2] = hscale(a[mt][2], att2[mt][0]);
                        au[mt][3] = hscale(a[mt][3], att2[mt][1]);
                    }
                }
#pragma unroll
                for (int p = 0; p < 4; p++) {
#pragma unroll
                    for (int mt = 0; mt < 2; mt++) {
                        mma_f16(c[mt][p * 2], au[mt], bfr[p][0], bfr[p][1]);
                        mma_f16(c[mt][p * 2 + 1], au[mt], bfr[p][2], bfr[p][3]);
                    }
                }
            }
        }
        __syncthreads();
    }

    // fused epilogue
#pragma unroll
    for (int nt = 0; nt < 8; nt++) {
        int col = wc * 64 + nt * 8 + 2 * t;
        float2 bi = *(const float2*)(bias + col);
        float2 mn = *(const float2*)(mean + col);
        float2 vr = *(const float2*)(var + col);
        float2 gm = *(const float2*)(gamma + col);
        float2 bt = *(const float2*)(beta + col);
        float sc0 = rsqrtf(vr.x + 1e-5f) * gm.x;
        float sc1 = rsqrtf(vr.y + 1e-5f) * gm.y;
        float sh0 = bt.x - mn.x * sc0;
        float sh1 = bt.y - mn.y * sc1;
#pragma unroll
        for (int mt = 0; mt < 2; mt++) {
#pragma unroll
            for (int p = 0; p < 2; p++) {
                int rloc = wr * 32 + mt * 16 + gid + p * 8;
                int r = rowBlock + rloc;
                if (r < NN) {
                    float sn = ssn[rloc];
                    float v0 = (c[mt][nt][p * 2 + 0] + bi.x) * sn;
                    float v1 = (c[mt][nt][p * 2 + 1] + bi.y) * sn;
                    v0 = fmaxf(fmaf(v0, sc0, sh0), 0.f);
                    v1 = fmaxf(fmaf(v1, sc1, sh1), 0.f);
                    float2 hres = *(const float2*)(h + (size_t)r * D + col);
                    *(float2*)(out + (size_t)r * D + col) =
                        make_float2(hres.x + v0, hres.y + v1);
                }
            }
        }
    }
}

// ---------------- launch ----------------------------------------------------
extern "C" void kernel_launch(void* const* d_in, const int* in_sizes, int n_in,
                              void* d_out, int out_size) {
    const float* h = (const float*)d_in[0];
    const float* eig = (const float*)d_in[1];
    const float* snorm = (const float*)d_in[2];
    const float* W = (const float*)d_in[3];
    const float* bias = (const float*)d_in[4];
    const float* gamma = (const float*)d_in[5];
    const float* beta = (const float*)d_in[6];
    const float* mean = (const float*)d_in[7];
    const float* var = (const float*)d_in[8];
    const int* esrc = (const int*)d_in[9];
    const int* edst = (const int*)d_in[10];
    float* out = (float*)d_out;

    // Host-side, non-stream, idempotent: safe under graph capture (no guard).
    cudaFuncSetAttribute(k_gemm, cudaFuncAttributeMaxDynamicSharedMemorySize,
                         SMEM_BYTES);

    k_prep<<<(NN * 64 + 255) / 256, 256>>>((const float2*)h, eig, (const float2*)W);
    k_fill<<<(EE / 4 + 255) / 256, 256>>>((const int4*)esrc, (const int4*)edst);
    k_reduce<<<(NN + 7) / 8, 256>>>();
    k_gemm<<<(NN + BM - 1) / BM, 256, SMEM_BYTES>>>(h, snorm, bias, gamma, beta,
                                                    mean, var, out);
}

// round 7
// speedup vs baseline: 1.2136x; 1.0094x over previous
#include <cuda_runtime.h>
#include <cuda_fp16.h>
#include <math.h>
#include <stdint.h>

#define NN 50000
#define EE 1600000
#define D 128
#define DAGG 384
#define DCAT 1152
#define CAP 128
#define AVG_D_LOG_F 3.4965075614664802f

// ---------------- static scratch --------------------------------------------
__device__ int g_cnt[NN];
__device__ int g_srcl[(size_t)NN * CAP];
__device__ float g_e1[NN];
__device__ __align__(16) __half g_hh[(size_t)NN * D];       // h in fp16
__device__ __align__(16) __half g_aggh[(size_t)NN * DAGG];  // agg fp16 [N,384]
__device__ __align__(16) __half g_Wh[(size_t)DCAT * D];     // W in fp16 [1152,128]

// ---------------- helpers ---------------------------------------------------
__device__ __forceinline__ float4 h4conv(uint2 u) {
    __half2 a = *reinterpret_cast<__half2*>(&u.x);
    __half2 b = *reinterpret_cast<__half2*>(&u.y);
    float2 fa = __half22float2(a);
    float2 fb = __half22float2(b);
    return make_float4(fa.x, fa.y, fb.x, fb.y);
}

__device__ __forceinline__ uint2 pack4(float4 v) {
    uint2 r;
    __half2 lo = __floats2half2_rn(v.x, v.y);
    __half2 hi = __floats2half2_rn(v.z, v.w);
    r.x = *reinterpret_cast<uint32_t*>(&lo);
    r.y = *reinterpret_cast<uint32_t*>(&hi);
    return r;
}

__device__ __forceinline__ void mma_f16(float* c, const uint32_t* a,
                                        uint32_t b0, uint32_t b1) {
    asm volatile(
        "mma.sync.aligned.m16n8k16.row.col.f32.f16.f16.f32 "
        "{%0,%1,%2,%3}, {%4,%5,%6,%7}, {%8,%9}, {%0,%1,%2,%3};\n"
        : "+f"(c[0]), "+f"(c[1]), "+f"(c[2]), "+f"(c[3])
        : "r"(a[0]), "r"(a[1]), "r"(a[2]), "r"(a[3]), "r"(b0), "r"(b1));
}

__device__ __forceinline__ void ldm_x4(uint32_t* r, uint32_t addr) {
    asm volatile("ldmatrix.sync.aligned.m8n8.x4.shared.b16 {%0,%1,%2,%3}, [%4];"
                 : "=r"(r[0]), "=r"(r[1]), "=r"(r[2]), "=r"(r[3]) : "r"(addr));
}

__device__ __forceinline__ void ldm_x4t(uint32_t* r, uint32_t addr) {
    asm volatile("ldmatrix.sync.aligned.m8n8.x4.trans.shared.b16 {%0,%1,%2,%3}, [%4];"
                 : "=r"(r[0]), "=r"(r[1]), "=r"(r[2]), "=r"(r[3]) : "r"(addr));
}

__device__ __forceinline__ void cp16(uint32_t smem_addr, const void* gptr) {
    asm volatile("cp.async.cg.shared.global [%0], [%1], 16;\n"
                 :: "r"(smem_addr), "l"(gptr));
}

__device__ __forceinline__ uint32_t hscale(uint32_t a, uint32_t coef2) {
    __half2 r = __hmul2(*reinterpret_cast<__half2*>(&a),
                        *reinterpret_cast<__half2*>(&coef2));
    return *reinterpret_cast<uint32_t*>(&r);
}

// ---------------- kernel 1: prep --------------------------------------------
__global__ void k_prep(const float2* __restrict__ h2in, const float* __restrict__ eig,
                       const float2* __restrict__ W2) {
    int idx = blockIdx.x * blockDim.x + threadIdx.x;
    if (idx < NN * 64) {
        float2 v = h2in[idx];
        reinterpret_cast<__half2*>(g_hh)[idx] = __floats2half2_rn(v.x, v.y);
    }
    if (idx < DCAT * 64) {
        float2 v = W2[idx];
        reinterpret_cast<__half2*>(g_Wh)[idx] = __floats2half2_rn(v.x, v.y);
    }
    if (idx < NN) {
        g_cnt[idx] = 0;
        g_e1[idx] = eig[(size_t)idx * 4];
    }
}

// ---------------- kernel 2: bucket fill --------------------------------------
__global__ void k_fill(const int4* __restrict__ src4, const int4* __restrict__ dst4) {
    int i = blockIdx.x * blockDim.x + threadIdx.x;
    if (i >= EE / 4) return;
    int4 d = dst4[i];
    int4 s = src4[i];
    int p0 = atomicAdd(&g_cnt[d.x], 1);
    int p1 = atomicAdd(&g_cnt[d.y], 1);
    int p2 = atomicAdd(&g_cnt[d.z], 1);
    int p3 = atomicAdd(&g_cnt[d.w], 1);
    g_srcl[(size_t)d.x * CAP + p0] = s.x;
    g_srcl[(size_t)d.y * CAP + p1] = s.y;
    g_srcl[(size_t)d.z * CAP + p2] = s.z;
    g_srcl[(size_t)d.w * CAP + p3] = s.w;
}

// ---------------- kernel 3: warp-per-node reduce (4-edge ILP) ----------------
__global__ __launch_bounds__(256) void k_reduce() {
    int wid = threadIdx.x >> 5;
    int lane = threadIdx.x & 31;
    int node = blockIdx.x * 8 + wid;
    if (node >= NN) return;
    int deg = g_cnt[node];
    size_t base = (size_t)node * CAP;
    float e1d = g_e1[node];
    const uint2* h2 = reinterpret_cast<const uint2*>(g_hh);

    float sx = 0.f, sy = 0.f, sz = 0.f, sw = 0.f;
    float mxx = -3.402823466e38f, mxy = mxx, mxz = mxx, mxw = mxx;
    float dx = 0.f, dy = 0.f, dz = 0.f, dw = 0.f;
    float wsum = 0.f;

    int j = 0;
    for (; j + 4 <= deg; j += 4) {
        int s0 = g_srcl[base + j];
        int s1 = g_srcl[base + j + 1];
        int s2 = g_srcl[base + j + 2];
        int s3 = g_srcl[base + j + 3];
        float w0 = fabsf(g_e1[s0] - e1d);
        float w1 = fabsf(g_e1[s1] - e1d);
        float w2 = fabsf(g_e1[s2] - e1d);
        float w3 = fabsf(g_e1[s3] - e1d);
        uint2 u0 = h2[(size_t)s0 * 32 + lane];
        uint2 u1 = h2[(size_t)s1 * 32 + lane];
        uint2 u2 = h2[(size_t)s2 * 32 + lane];
        uint2 u3 = h2[(size_t)s3 * 32 + lane];
        float4 v0 = h4conv(u0);
        float4 v1 = h4conv(u1);
        float4 v2 = h4conv(u2);
        float4 v3 = h4conv(u3);
        sx += v0.x + v1.x + v2.x + v3.x;
        sy += v0.y + v1.y + v2.y + v3.y;
        sz += v0.z + v1.z + v2.z + v3.z;
        sw += v0.w + v1.w + v2.w + v3.w;
        mxx = fmaxf(fmaxf(mxx, fmaxf(v0.x, v1.x)), fmaxf(v2.x, v3.x));
        mxy = fmaxf(fmaxf(mxy, fmaxf(v0.y, v1.y)), fmaxf(v2.y, v3.y));
        mxz = fmaxf(fmaxf(mxz, fmaxf(v0.z, v1.z)), fmaxf(v2.z, v3.z));
        mxw = fmaxf(fmaxf(mxw, fmaxf(v0.w, v1.w)), fmaxf(v2.w, v3.w));
        dx = fmaf(w0, v0.x, fmaf(w1, v1.x, fmaf(w2, v2.x, fmaf(w3, v3.x, dx))));
        dy = fmaf(w0, v0.y, fmaf(w1, v1.y, fmaf(w2, v2.y, fmaf(w3, v3.y, dy))));
        dz = fmaf(w0, v0.z, fmaf(w1, v1.z, fmaf(w2, v2.z, fmaf(w3, v3.z, dz))));
        dw = fmaf(w0, v0.w, fmaf(w1, v1.w, fmaf(w2, v2.w, fmaf(w3, v3.w, dw))));
        wsum += w0 + w1 + w2 + w3;
    }
    for (; j < deg; j++) {
        int s0 = g_srcl[base + j];
        float w0 = fabsf(g_e1[s0] - e1d);
        float4 v0 = h4conv(h2[(size_t)s0 * 32 + lane]);
        sx += v0.x; sy += v0.y; sz += v0.z; sw += v0.w;
        mxx = fmaxf(mxx, v0.x); mxy = fmaxf(mxy, v0.y);
        mxz = fmaxf(mxz, v0.z); mxw = fmaxf(mxw, v0.w);
        dx = fmaf(w0, v0.x, dx); dy = fmaf(w0, v0.y, dy);
        dz = fmaf(w0, v0.z, dz); dw = fmaf(w0, v0.w, dw);
        wsum += w0;
    }

    float invd = 1.f / (float)(deg > 0 ? deg : 1);
    float invw = 1.f / (wsum + 1e-30f);
    if (deg == 0) { mxx = 0.f; mxy = 0.f; mxz = 0.f; mxw = 0.f; }

    uint2* o = reinterpret_cast<uint2*>(g_aggh) + (size_t)node * 96;
    o[lane]      = pack4(make_float4(sx * invd, sy * invd, sz * invd, sw * invd));
    o[32 + lane] = pack4(make_float4(mxx, mxy, mxz, mxw));
    o[64 + lane] = pack4(make_float4(dx * invw, dy * invw, dz * invw, dw * invw));
}

// ---------------- kernel 4: fused triple-B GEMM + epilogue -------------------
// Tile: BM=128 rows x BN=64 cols; grid = 391 row blocks x 2 col blocks.
// out[r,c] = epi( sum_g coef_g(r) * (agg[r,:] @ W[g*384:(g+1)*384, c]) )
#define BM 128
#define BN 64
#define BK 32
#define NKT (DAGG / BK)  // 12
// smem (halfs): As 2*128*40 = 10240 ; Bs 2*3*32*72 = 13824 ; + 384 floats
#define SM_BS 10240
#define SM_COEF 24064
#define SMEM_BYTES (24064 * 2 + 3 * 128 * 4)  // 49664

__global__ __launch_bounds__(256, 3) void k_gemm(
    const float* __restrict__ h, const float* __restrict__ snorm,
    const float* __restrict__ bias, const float* __restrict__ gamma,
    const float* __restrict__ beta, const float* __restrict__ mean,
    const float* __restrict__ var, float* __restrict__ out) {
    extern __shared__ __half sh[];
    __half* As = sh;                         // [2][128][40]
    __half* Bs = sh + SM_BS;                 // [2][3][32][72]
    float* samp = (float*)(sh + SM_COEF);    // [128]
    float* satt = samp + BM;
    float* ssn = satt + BM;

    int tid = threadIdx.x;
    int wid = tid >> 5;
    int lane = tid & 31;
    int t = lane & 3;
    int gid = lane >> 2;
    int wr = wid & 3;   // rows wr*32
    int wc = wid >> 2;  // cols wc*32 (0..1)
    int rowBlock = (blockIdx.x >> 1) * BM;
    int colBlock = (blockIdx.x & 1) * BN;

    // per-row scaler coefficients
    for (int i = tid; i < BM; i += 256) {
        int r = rowBlock + i;
        float amp = 0.f, att = 0.f, sn = 0.f;
        if (r < NN) {
            int deg = g_cnt[r];
            float logD = logf((float)deg + 1.0f);
            amp = logD * (1.0f / AVG_D_LOG_F);
            att = fminf(AVG_D_LOG_F / fmaxf(logD, 1e-6f), 60000.f);
            sn = snorm[r];
        }
        samp[i] = amp;
        satt[i] = att;
        ssn[i] = sn;
    }

    // A async-copy lanes: 2 chunks/thread (rows tid>>2 and +64, chunk tid&3)
    int a_row = tid >> 2, a_chk = tid & 3;
    int ar0 = rowBlock + a_row; if (ar0 > NN - 1) ar0 = NN - 1;
    int ar1 = rowBlock + a_row + 64; if (ar1 > NN - 1) ar1 = NN - 1;
    const __half* a_src0 = g_aggh + (size_t)ar0 * DAGG + a_chk * 8;
    const __half* a_src1 = g_aggh + (size_t)ar1 * DAGG + a_chk * 8;
    uint32_t a_dst0 = (uint32_t)__cvta_generic_to_shared(As + a_row * 40 + a_chk * 8);
    uint32_t a_dst1 = a_dst0 + 64 * 80;

    // B async-copy lanes: 3 chunks/thread over [3][32][8] (8 chunks of 8 halfs)
    const __half* b_src[3];
    uint32_t b_dst[3];
#pragma unroll
    for (int i = 0; i < 3; i++) {
        int idx = tid + 256 * i;
        int g = idx >> 8;
        int rem = idx & 255;
        int row = rem >> 3;
        int col = rem & 7;
        b_src[i] = g_Wh + ((size_t)g * DAGG + row) * D + colBlock + col * 8;
        b_dst[i] = (uint32_t)__cvta_generic_to_shared(
            Bs + g * 2304 + row * 72 + col * 8);
    }

    float c[2][4][4];
#pragma unroll
    for (int mt = 0; mt < 2; mt++)
#pragma unroll
        for (int nt = 0; nt < 4; nt++)
#pragma unroll
            for (int k = 0; k < 4; k++) c[mt][nt][k] = 0.f;

    // prefetch tile 0 (buf 0)
    cp16(a_dst0, a_src0);
    cp16(a_dst1, a_src1);
#pragma unroll
    for (int i = 0; i < 3; i++) cp16(b_dst[i], b_src[i]);
    asm volatile("cp.async.commit_group;\n");

    __syncthreads();  // coef arrays visible

    // per-thread coef half2 broadcasts (rows wr*32 + mt*16 + gid / +8)
    uint32_t amp2[2][2], att2[2][2];
#pragma unroll
    for (int mt = 0; mt < 2; mt++) {
        int r0 = wr * 32 + mt * 16 + gid;
        __half2 a0 = __float2half2_rn(samp[r0]);
        __half2 a1 = __float2half2_rn(samp[r0 + 8]);
        __half2 t0 = __float2half2_rn(satt[r0]);
        __half2 t1 = __float2half2_rn(satt[r0 + 8]);
        amp2[mt][0] = *reinterpret_cast<uint32_t*>(&a0);
        amp2[mt][1] = *reinterpret_cast<uint32_t*>(&a1);
        att2[mt][0] = *reinterpret_cast<uint32_t*>(&t0);
        att2[mt][1] = *reinterpret_cast<uint32_t*>(&t1);
    }

    // ldmatrix base addresses (buf 0)
    uint32_t a_lm = (uint32_t)__cvta_generic_to_shared(
        As + (wr * 32 + (lane & 15)) * 40 + ((lane >> 4) << 3));
    uint32_t b_lm = (uint32_t)__cvta_generic_to_shared(
        Bs + (lane & 15) * 72 + wc * 32 + ((lane >> 4) << 3));

    for (int kt = 0; kt < NKT; kt++) {
        int buf = kt & 1;
        if (kt + 1 < NKT) {
            size_t koff = (size_t)(kt + 1) * BK;
            uint32_t abufo = (buf ^ 1) * 10240;  // bytes: 128*40*2
            cp16(a_dst0 + abufo, a_src0 + koff);
            cp16(a_dst1 + abufo, a_src1 + koff);
            uint32_t bbufo = (buf ^ 1) * 13824;  // bytes: 3*32*72*2
#pragma unroll
            for (int i = 0; i < 3; i++)
                cp16(b_dst[i] + bbufo, b_src[i] + koff * D);
            asm volatile("cp.async.commit_group;\n");
            asm volatile("cp.async.wait_group 1;\n");
        } else {
            asm volatile("cp.async.wait_group 0;\n");
        }
        __syncthreads();

        uint32_t a_base = a_lm + buf * 10240;
        uint32_t b_base = b_lm + buf * 13824;
#pragma unroll
        for (int ks = 0; ks < 2; ks++) {
            uint32_t a[2][4];
            ldm_x4(a[0], a_base + ks * 32);
            ldm_x4(a[1], a_base + 16 * 80 + ks * 32);
#pragma unroll
            for (int g = 0; g < 3; g++) {
                uint32_t bfr[2][4];
#pragma unroll
                for (int p = 0; p < 2; p++)
                    ldm_x4t(bfr[p], b_base + g * 4608 + ks * 16 * 144 + p * 32);
                uint32_t au[2][4];
#pragma unroll
                for (int mt = 0; mt < 2; mt++) {
                    if (g == 0) {
                        au[mt][0] = a[mt][0]; au[mt][1] = a[mt][1];
                        au[mt][2] = a[mt][2]; au[mt][3] = a[mt][3];
                    } else if (g == 1) {
                        au[mt][0] = hscale(a[mt][0], amp2[mt][0]);
                        au[mt][1] = hscale(a[mt][1], amp2[mt][1]);
                        au[mt][2] = hscale(a[mt][2], amp2[mt][0]);
                        au[mt][3] = hscale(a[mt][3], amp2[mt][1]);
                    } else {
                        au[mt][0] = hscale(a[mt][0], att2[mt][0]);
                        au[mt][1] = hscale(a[mt][1], att2[mt][1]);
                        au[mt][2] = hscale(a[mt][2], att2[mt][0]);
                        au[mt][3] = hscale(a[mt][3], att2[mt][1]);
                    }
                }
#pragma unroll
                for (int p = 0; p < 2; p++) {
#pragma unroll
                    for (int mt = 0; mt < 2; mt++) {
                        mma_f16(c[mt][p * 2], au[mt], bfr[p][0], bfr[p][1]);
                        mma_f16(c[mt][p * 2 + 1], au[mt], bfr[p][2], bfr[p][3]);
                    }
                }
            }
        }
        __syncthreads();
    }

    // fused epilogue
#pragma unroll
    for (int nt = 0; nt < 4; nt++) {
        int col = colBlock + wc * 32 + nt * 8 + 2 * t;
        float2 bi = *(const float2*)(bias + col);
        float2 mn = *(const float2*)(mean + col);
        float2 vr = *(const float2*)(var + col);
        float2 gm = *(const float2*)(gamma + col);
        float2 bt = *(const float2*)(beta + col);
        float sc0 = rsqrtf(vr.x + 1e-5f) * gm.x;
        float sc1 = rsqrtf(vr.y + 1e-5f) * gm.y;
        float sh0 = bt.x - mn.x * sc0;
        float sh1 = bt.y - mn.y * sc1;
#pragma unroll
        for (int mt = 0; mt < 2; mt++) {
#pragma unroll
            for (int p = 0; p < 2; p++) {
                int rloc = wr * 32 + mt * 16 + gid + p * 8;
                int r = rowBlock + rloc;
                if (r < NN) {
                    float sn = ssn[rloc];
                    float v0 = (c[mt][nt][p * 2 + 0] + bi.x) * sn;
                    float v1 = (c[mt][nt][p * 2 + 1] + bi.y) * sn;
                    v0 = fmaxf(fmaf(v0, sc0, sh0), 0.f);
                    v1 = fmaxf(fmaf(v1, sc1, sh1), 0.f);
                    float2 hres = *(const float2*)(h + (size_t)r * D + col);
                    *(float2*)(out + (size_t)r * D + col) =
                        make_float2(hres.x + v0, hres.y + v1);
                }
            }
        }
    }
}

// ---------------- launch ----------------------------------------------------
extern "C" void kernel_launch(void* const* d_in, const int* in_sizes, int n_in,
                              void* d_out, int out_size) {
    const float* h = (const float*)d_in[0];
    const float* eig = (const float*)d_in[1];
    const float* snorm = (const float*)d_in[2];
    const float* W = (const float*)d_in[3];
    const float* bias = (const float*)d_in[4];
    const float* gamma = (const float*)d_in[5];
    const float* beta = (const float*)d_in[6];
    const float* mean = (const float*)d_in[7];
    const float* var = (const float*)d_in[8];
    const int* esrc = (const int*)d_in[9];
    const int* edst = (const int*)d_in[10];
    float* out = (float*)d_out;

    // Host-side, non-stream, idempotent: safe under graph capture (no guard).
    cudaFuncSetAttribute(k_gemm, cudaFuncAttributeMaxDynamicSharedMemorySize,
                         SMEM_BYTES);

    k_prep<<<(NN * 64 + 255) / 256, 256>>>((const float2*)h, eig, (const float2*)W);
    k_fill<<<(EE / 4 + 255) / 256, 256>>>((const int4*)esrc, (const int4*)edst);
    k_reduce<<<(NN + 7) / 8, 256>>>();
    k_gemm<<<((NN + BM - 1) / BM) * 2, 256, SMEM_BYTES>>>(h, snorm, bias, gamma,
                                                          beta, mean, var, out);
}

// round 9
// speedup vs baseline: 1.2335x; 1.0164x over previous
#include <cuda_runtime.h>
#include <cuda_fp16.h>
#include <math.h>
#include <stdint.h>

#define NN 50000
#define EE 1600000
#define D 128
#define DAGG 384
#define DCAT 1152
#define CAP 128
#define AVG_D_LOG_F 3.4965075614664802f

// ---------------- static scratch --------------------------------------------
__device__ int g_cnt[NN];
__device__ int g_srcl[(size_t)NN * CAP];
__device__ float g_e1[NN];
__device__ __align__(16) __half g_hh[(size_t)NN * D];       // h in fp16
__device__ __align__(16) __half g_aggh[(size_t)NN * DAGG];  // agg fp16 [N,384]
__device__ __align__(16) __half g_Wh[(size_t)DCAT * D];     // W in fp16 [1152,128]

// ---------------- helpers ---------------------------------------------------
__device__ __forceinline__ float4 h4conv(uint2 u) {
    __half2 a = *reinterpret_cast<__half2*>(&u.x);
    __half2 b = *reinterpret_cast<__half2*>(&u.y);
    float2 fa = __half22float2(a);
    float2 fb = __half22float2(b);
    return make_float4(fa.x, fa.y, fb.x, fb.y);
}

__device__ __forceinline__ uint2 pack4(float4 v) {
    uint2 r;
    __half2 lo = __floats2half2_rn(v.x, v.y);
    __half2 hi = __floats2half2_rn(v.z, v.w);
    r.x = *reinterpret_cast<uint32_t*>(&lo);
    r.y = *reinterpret_cast<uint32_t*>(&hi);
    return r;
}

__device__ __forceinline__ void mma_f16(float* c, const uint32_t* a,
                                        uint32_t b0, uint32_t b1) {
    asm volatile(
        "mma.sync.aligned.m16n8k16.row.col.f32.f16.f16.f32 "
        "{%0,%1,%2,%3}, {%4,%5,%6,%7}, {%8,%9}, {%0,%1,%2,%3};\n"
        : "+f"(c[0]), "+f"(c[1]), "+f"(c[2]), "+f"(c[3])
        : "r"(a[0]), "r"(a[1]), "r"(a[2]), "r"(a[3]), "r"(b0), "r"(b1));
}

__device__ __forceinline__ void ldm_x4(uint32_t* r, uint32_t addr) {
    asm volatile("ldmatrix.sync.aligned.m8n8.x4.shared.b16 {%0,%1,%2,%3}, [%4];"
                 : "=r"(r[0]), "=r"(r[1]), "=r"(r[2]), "=r"(r[3]) : "r"(addr));
}

__device__ __forceinline__ void ldm_x4t(uint32_t* r, uint32_t addr) {
    asm volatile("ldmatrix.sync.aligned.m8n8.x4.trans.shared.b16 {%0,%1,%2,%3}, [%4];"
                 : "=r"(r[0]), "=r"(r[1]), "=r"(r[2]), "=r"(r[3]) : "r"(addr));
}

__device__ __forceinline__ void cp16(uint32_t smem_addr, const void* gptr) {
    asm volatile("cp.async.cg.shared.global [%0], [%1], 16;\n"
                 :: "r"(smem_addr), "l"(gptr));
}

__device__ __forceinline__ uint32_t hscale(uint32_t a, uint32_t coef2) {
    __half2 r = __hmul2(*reinterpret_cast<__half2*>(&a),
                        *reinterpret_cast<__half2*>(&coef2));
    return *reinterpret_cast<uint32_t*>(&r);
}

// ---------------- kernel 1: fused prep + bucket fill -------------------------
// role-split by blockIdx: [0,FILLB) edge fill; then h->fp16; then W->fp16; then e1.
#define FILLB 1563    // ceil(400000/256) threads x 4 edges
#define HCONVB 3125   // 800000 threads x 2 float4
#define WCONVB 576    // 147456 elems
#define E1B 196       // 50176 threads
#define PREPGRID (FILLB + HCONVB + WCONVB + E1B)

__global__ void k_prepfill(const int4* __restrict__ src4, const int4* __restrict__ dst4,
                           const float* __restrict__ h, const float* __restrict__ eig,
                           const float* __restrict__ W) {
    int b = blockIdx.x;
    int t = threadIdx.x;
    if (b < FILLB) {
        int i = b * 256 + t;
        if (i >= EE / 4) return;
        int4 d = dst4[i];
        int4 s = src4[i];
        int p0 = atomicAdd(&g_cnt[d.x], 1);
        int p1 = atomicAdd(&g_cnt[d.y], 1);
        int p2 = atomicAdd(&g_cnt[d.z], 1);
        int p3 = atomicAdd(&g_cnt[d.w], 1);
        g_srcl[(size_t)d.x * CAP + p0] = s.x;
        g_srcl[(size_t)d.y * CAP + p1] = s.y;
        g_srcl[(size_t)d.z * CAP + p2] = s.z;
        g_srcl[(size_t)d.w * CAP + p3] = s.w;
    } else if (b < FILLB + HCONVB) {
        int i = (b - FILLB) * 256 + t;  // 0..799999
        const float4* h4 = (const float4*)h;
        uint2* o = (uint2*)g_hh;
#pragma unroll
        for (int r = 0; r < 2; r++) {
            int idx = i + r * 800000;   // < 1600000
            float4 v = h4[idx];
            o[idx] = pack4(v);
        }
    } else if (b < FILLB + HCONVB + WCONVB) {
        int idx = (b - FILLB - HCONVB) * 256 + t;
        if (idx < DCAT * D)
            g_Wh[idx] = __float2half(W[idx]);
    } else {
        int idx = (b - FILLB - HCONVB - WCONVB) * 256 + t;
        if (idx < NN) g_e1[idx] = eig[(size_t)idx * 4];
    }
}

// ---------------- kernel 2: warp-per-node reduce (4-edge ILP) ----------------
__global__ __launch_bounds__(256) void k_reduce() {
    int wid = threadIdx.x >> 5;
    int lane = threadIdx.x & 31;
    int node = blockIdx.x * 8 + wid;
    if (node >= NN) return;
    int deg = g_cnt[node];
    size_t base = (size_t)node * CAP;
    float e1d = g_e1[node];
    const uint2* h2 = reinterpret_cast<const uint2*>(g_hh);

    float sx = 0.f, sy = 0.f, sz = 0.f, sw = 0.f;
    float mxx = -3.402823466e38f, mxy = mxx, mxz = mxx, mxw = mxx;
    float dx = 0.f, dy = 0.f, dz = 0.f, dw = 0.f;
    float wsum = 0.f;

    int j = 0;
    for (; j + 4 <= deg; j += 4) {
        int s0 = g_srcl[base + j];
        int s1 = g_srcl[base + j + 1];
        int s2 = g_srcl[base + j + 2];
        int s3 = g_srcl[base + j + 3];
        float w0 = fabsf(g_e1[s0] - e1d);
        float w1 = fabsf(g_e1[s1] - e1d);
        float w2 = fabsf(g_e1[s2] - e1d);
        float w3 = fabsf(g_e1[s3] - e1d);
        float4 v0 = h4conv(h2[(size_t)s0 * 32 + lane]);
        float4 v1 = h4conv(h2[(size_t)s1 * 32 + lane]);
        float4 v2 = h4conv(h2[(size_t)s2 * 32 + lane]);
        float4 v3 = h4conv(h2[(size_t)s3 * 32 + lane]);
        sx += v0.x + v1.x + v2.x + v3.x;
        sy += v0.y + v1.y + v2.y + v3.y;
        sz += v0.z + v1.z + v2.z + v3.z;
        sw += v0.w + v1.w + v2.w + v3.w;
        mxx = fmaxf(fmaxf(mxx, fmaxf(v0.x, v1.x)), fmaxf(v2.x, v3.x));
        mxy = fmaxf(fmaxf(mxy, fmaxf(v0.y, v1.y)), fmaxf(v2.y, v3.y));
        mxz = fmaxf(fmaxf(mxz, fmaxf(v0.z, v1.z)), fmaxf(v2.z, v3.z));
        mxw = fmaxf(fmaxf(mxw, fmaxf(v0.w, v1.w)), fmaxf(v2.w, v3.w));
        dx = fmaf(w0, v0.x, fmaf(w1, v1.x, fmaf(w2, v2.x, fmaf(w3, v3.x, dx))));
        dy = fmaf(w0, v0.y, fmaf(w1, v1.y, fmaf(w2, v2.y, fmaf(w3, v3.y, dy))));
        dz = fmaf(w0, v0.z, fmaf(w1, v1.z, fmaf(w2, v2.z, fmaf(w3, v3.z, dz))));
        dw = fmaf(w0, v0.w, fmaf(w1, v1.w, fmaf(w2, v2.w, fmaf(w3, v3.w, dw))));
        wsum += w0 + w1 + w2 + w3;
    }
    for (; j < deg; j++) {
        int s0 = g_srcl[base + j];
        float w0 = fabsf(g_e1[s0] - e1d);
        float4 v0 = h4conv(h2[(size_t)s0 * 32 + lane]);
        sx += v0.x; sy += v0.y; sz += v0.z; sw += v0.w;
        mxx = fmaxf(mxx, v0.x); mxy = fmaxf(mxy, v0.y);
        mxz = fmaxf(mxz, v0.z); mxw = fmaxf(mxw, v0.w);
        dx = fmaf(w0, v0.x, dx); dy = fmaf(w0, v0.y, dy);
        dz = fmaf(w0, v0.z, dz); dw = fmaf(w0, v0.w, dw);
        wsum += w0;
    }

    float invd = 1.f / (float)(deg > 0 ? deg : 1);
    float invw = 1.f / (wsum + 1e-30f);
    if (deg == 0) { mxx = 0.f; mxy = 0.f; mxz = 0.f; mxw = 0.f; }

    uint2* o = reinterpret_cast<uint2*>(g_aggh) + (size_t)node * 96;
    o[lane]      = pack4(make_float4(sx * invd, sy * invd, sz * invd, sw * invd));
    o[32 + lane] = pack4(make_float4(mxx, mxy, mxz, mxw));
    o[64 + lane] = pack4(make_float4(dx * invw, dy * invw, dz * invw, dw * invw));
}

// ---------------- kernel 3: fused triple-B GEMM + epilogue, 3-stage pipe -----
// Tile: BM=128 rows x BN=64 cols; grid = 391 row blocks x 2 col blocks.
// out[r,c] = epi( sum_g coef_g(r) * (agg[r,:] @ W[g*384:(g+1)*384, c]) )
#define BM 128
#define BN 64
#define BK 32
#define NKT (DAGG / BK)  // 12
#define NSTG 3
// smem (halfs): As 3*128*40 = 15360 ; Bs 3*3*32*72 = 20736 ; + 384 floats
#define SM_BS 15360
#define SM_COEF 36096
#define SMEM_BYTES (36096 * 2 + 3 * 128 * 4)  // 73728

__global__ __launch_bounds__(256, 3) void k_gemm(
    const float* __restrict__ h, const float* __restrict__ snorm,
    const float* __restrict__ bias, const float* __restrict__ gamma,
    const float* __restrict__ beta, const float* __restrict__ mean,
    const float* __restrict__ var, float* __restrict__ out) {
    extern __shared__ __half sh[];
    __half* As = sh;                         // [3][128][40]
    __half* Bs = sh + SM_BS;                 // [3][3][32][72]
    float* samp = (float*)(sh + SM_COEF);    // [128]
    float* satt = samp + BM;
    float* ssn = satt + BM;

    int tid = threadIdx.x;
    int wid = tid >> 5;
    int lane = tid & 31;
    int t = lane & 3;
    int gid = lane >> 2;
    int wr = wid & 3;   // rows wr*32
    int wc = wid >> 2;  // cols wc*32 (0..1)
    int rowBlock = (blockIdx.x >> 1) * BM;
    int colBlock = (blockIdx.x & 1) * BN;

    // per-row scaler coefficients
    for (int i = tid; i < BM; i += 256) {
        int r = rowBlock + i;
        float amp = 0.f, att = 0.f, sn = 0.f;
        if (r < NN) {
            int deg = g_cnt[r];
            float logD = logf((float)deg + 1.0f);
            amp = logD * (1.0f / AVG_D_LOG_F);
            att = fminf(AVG_D_LOG_F / fmaxf(logD, 1e-6f), 60000.f);
            sn = snorm[r];
        }
        samp[i] = amp;
        satt[i] = att;
        ssn[i] = sn;
    }

    // A async-copy lanes: 2 chunks/thread (rows tid>>2 and +64, chunk tid&3)
    int a_row = tid >> 2, a_chk = tid & 3;
    int ar0 = rowBlock + a_row; if (ar0 > NN - 1) ar0 = NN - 1;
    int ar1 = rowBlock + a_row + 64; if (ar1 > NN - 1) ar1 = NN - 1;
    const __half* a_src0 = g_aggh + (size_t)ar0 * DAGG + a_chk * 8;
    const __half* a_src1 = g_aggh + (size_t)ar1 * DAGG + a_chk * 8;
    uint32_t a_dst0 = (uint32_t)__cvta_generic_to_shared(As + a_row * 40 + a_chk * 8);
    uint32_t a_dst1 = a_dst0 + 64 * 80;

    // B async-copy lanes: 3 chunks/thread over [3][32][8]
    const __half* b_src[3];
    uint32_t b_dst[3];
#pragma unroll
    for (int i = 0; i < 3; i++) {
        int idx = tid + 256 * i;
        int g = idx >> 8;
        int rem = idx & 255;
        int row = rem >> 3;
        int col = rem & 7;
        b_src[i] = g_Wh + ((size_t)g * DAGG + row) * D + colBlock + col * 8;
        b_dst[i] = (uint32_t)__cvta_generic_to_shared(
            Bs + g * 2304 + row * 72 + col * 8);
    }

    float c[2][4][4];
#pragma unroll
    for (int mt = 0; mt < 2; mt++)
#pragma unroll
        for (int nt = 0; nt < 4; nt++)
#pragma unroll
            for (int k = 0; k < 4; k++) c[mt][nt][k] = 0.f;

    // prologue: prefetch kt=0 and kt=1
#pragma unroll
    for (int pk = 0; pk < 2; pk++) {
        size_t koff = (size_t)pk * BK;
        uint32_t ao = pk * 10240;
        cp16(a_dst0 + ao, a_src0 + koff);
        cp16(a_dst1 + ao, a_src1 + koff);
        uint32_t bo = pk * 13824;
#pragma unroll
        for (int i = 0; i < 3; i++)
            cp16(b_dst[i] + bo, b_src[i] + koff * D);
        asm volatile("cp.async.commit_group;\n");
    }

    __syncthreads();  // coef arrays visible

    // per-thread coef half2 broadcasts (rows wr*32 + mt*16 + gid / +8)
    uint32_t amp2[2][2], att2[2][2];
#pragma unroll
    for (int mt = 0; mt < 2; mt++) {
        int r0 = wr * 32 + mt * 16 + gid;
        __half2 a0 = __float2half2_rn(samp[r0]);
        __half2 a1 = __float2half2_rn(samp[r0 + 8]);
        __half2 t0 = __float2half2_rn(satt[r0]);
        __half2 t1 = __float2half2_rn(satt[r0 + 8]);
        amp2[mt][0] = *reinterpret_cast<uint32_t*>(&a0);
        amp2[mt][1] = *reinterpret_cast<uint32_t*>(&a1);
        att2[mt][0] = *reinterpret_cast<uint32_t*>(&t0);
        att2[mt][1] = *reinterpret_cast<uint32_t*>(&t1);
    }

    // ldmatrix base addresses (buf 0)
    uint32_t a_lm = (uint32_t)__cvta_generic_to_shared(
        As + (wr * 32 + (lane & 15)) * 40 + ((lane >> 4) << 3));
    uint32_t b_lm = (uint32_t)__cvta_generic_to_shared(
        Bs + (lane & 15) * 72 + wc * 32 + ((lane >> 4) << 3));

    int buf = 0;
    for (int kt = 0; kt < NKT; kt++) {
        if (kt + 1 < NKT) {
            asm volatile("cp.async.wait_group 1;\n");
        } else {
            asm volatile("cp.async.wait_group 0;\n");
        }
        __syncthreads();

        // prefetch kt+2 into the buffer freed last iteration
        if (kt + 2 < NKT) {
            int nb = buf + 2; if (nb >= NSTG) nb -= NSTG;
            size_t koff = (size_t)(kt + 2) * BK;
            uint32_t ao = nb * 10240;
            cp16(a_dst0 + ao, a_src0 + koff);
            cp16(a_dst1 + ao, a_src1 + koff);
            uint32_t bo = nb * 13824;
#pragma unroll
            for (int i = 0; i < 3; i++)
                cp16(b_dst[i] + bo, b_src[i] + koff * D);
            asm volatile("cp.async.commit_group;\n");
        }

        uint32_t a_base = a_lm + buf * 10240;
        uint32_t b_base = b_lm + buf * 13824;
#pragma unroll
        for (int ks = 0; ks < 2; ks++) {
            uint32_t a[2][4];
            ldm_x4(a[0], a_base + ks * 32);
            ldm_x4(a[1], a_base + 16 * 80 + ks * 32);
#pragma unroll
            for (int g = 0; g < 3; g++) {
                uint32_t bfr[2][4];
#pragma unroll
                for (int p = 0; p < 2; p++)
                    ldm_x4t(bfr[p], b_base + g * 4608 + ks * 16 * 144 + p * 32);
                uint32_t au[2][4];
#pragma unroll
                for (int mt = 0; mt < 2; mt++) {
                    if (g == 0) {
                        au[mt][0] = a[mt][0]; au[mt][1] = a[mt][1];
                        au[mt][2] = a[mt][2]; au[mt][3] = a[mt][3];
                    } else if (g == 1) {
                        au[mt][0] = hscale(a[mt][0], amp2[mt][0]);
                        au[mt][1] = hscale(a[mt][1], amp2[mt][1]);
                        au[mt][2] = hscale(a[mt][2], amp2[mt][0]);
                        au[mt][3] = hscale(a[mt][3], amp2[mt][1]);
                    } else {
                        au[mt][0] = hscale(a[mt][0], att2[mt][0]);
                        au[mt][1] = hscale(a[mt][1], att2[mt][1]);
                        au[mt][2] = hscale(a[mt][2], att2[mt][0]);
                        au[mt][3] = hscale(a[mt][3], att2[mt][1]);
                    }
                }
#pragma unroll
                for (int p = 0; p < 2; p++) {
#pragma unroll
                    for (int mt = 0; mt < 2; mt++) {
                        mma_f16(c[mt][p * 2], au[mt], bfr[p][0], bfr[p][1]);
                        mma_f16(c[mt][p * 2 + 1], au[mt], bfr[p][2], bfr[p][3]);
                    }
                }
            }
        }
        __syncthreads();
        buf++; if (buf >= NSTG) buf = 0;
    }

    // fused epilogue
#pragma unroll
    for (int nt = 0; nt < 4; nt++) {
        int col = colBlock + wc * 32 + nt * 8 + 2 * t;
        float2 bi = *(const float2*)(bias + col);
        float2 mn = *(const float2*)(mean + col);
        float2 vr = *(const float2*)(var + col);
        float2 gm = *(const float2*)(gamma + col);
        float2 bt = *(const float2*)(beta + col);
        float sc0 = rsqrtf(vr.x + 1e-5f) * gm.x;
        float sc1 = rsqrtf(vr.y + 1e-5f) * gm.y;
        float sh0 = bt.x - mn.x * sc0;
        float sh1 = bt.y - mn.y * sc1;
#pragma unroll
        for (int mt = 0; mt < 2; mt++) {
#pragma unroll
            for (int p = 0; p < 2; p++) {
                int rloc = wr * 32 + mt * 16 + gid + p * 8;
                int r = rowBlock + rloc;
                if (r < NN) {
                    float sn = ssn[rloc];
                    float v0 = (c[mt][nt][p * 2 + 0] + bi.x) * sn;
                    float v1 = (c[mt][nt][p * 2 + 1] + bi.y) * sn;
                    v0 = fmaxf(fmaf(v0, sc0, sh0), 0.f);
                    v1 = fmaxf(fmaf(v1, sc1, sh1), 0.f);
                    float2 hres = *(const float2*)(h + (size_t)r * D + col);
                    *(float2*)(out + (size_t)r * D + col) =
                        make_float2(hres.x + v0, hres.y + v1);
                }
            }
        }
    }
}

// ---------------- launch ----------------------------------------------------
extern "C" void kernel_launch(void* const* d_in, const int* in_sizes, int n_in,
                              void* d_out, int out_size) {
    const float* h = (const float*)d_in[0];
    const float* eig = (const float*)d_in[1];
    const float* snorm = (const float*)d_in[2];
    const float* W = (const float*)d_in[3];
    const float* bias = (const float*)d_in[4];
    const float* gamma = (const float*)d_in[5];
    const float* beta = (const float*)d_in[6];
    const float* mean = (const float*)d_in[7];
    const float* var = (const float*)d_in[8];
    const int* esrc = (const int*)d_in[9];
    const int* edst = (const int*)d_in[10];
    float* out = (float*)d_out;

    // Host-side, non-stream, idempotent: capture-safe (no guard).
    cudaFuncSetAttribute(k_gemm, cudaFuncAttributeMaxDynamicSharedMemorySize,
                         SMEM_BYTES);

    // Zero bucket counters via an async memset node (capture-safe).
    void* cntPtr = nullptr;
    cudaGetSymbolAddress(&cntPtr, g_cnt);
    cudaMemsetAsync(cntPtr, 0, NN * sizeof(int));

    k_prepfill<<<PREPGRID, 256>>>((const int4*)esrc, (const int4*)edst, h, eig, W);
    k_reduce<<<(NN + 7) / 8, 256>>>();
    k_gemm<<<((NN + BM - 1) / BM) * 2, 256, SMEM_BYTES>>>(h, snorm, bias, gamma,
                                                          beta, mean, var, out);
}